// round 2
// baseline (speedup 1.0000x reference)
#include <cuda_runtime.h>

#define EPSF 1e-6f

constexpr int cV = 128, cK = 32, cC = 256;
constexpr int cL = 4, cN = 4096, cF = 16;
constexpr int cE = 8192, cB = 512;
constexpr int cB4 = cB / 4;          // 128 float4 groups per row
constexpr int GRID = 148;            // persistent blocks, 1/SM guaranteed resident
constexpr int NT   = 512;
constexpr float LN2F = 0.69314718055994530942f;

// ---- scratch (static __device__ per allocation rules) ----
__device__ __align__(16) float d_lwin[cV * cK * cC];   // 4 MB  (log2 domain)
__device__ __align__(16) float d_lwsum[cL * cN * cF];  // 1 MB  (log2 domain)
__device__ __align__(16) float d_lr[cN];               // 16 KB (log2 domain)
__device__ __align__(16) int   d_xT[cV * cB];          // 256 KB transposed inputs
__device__ __align__(16) float d_nmA[cN * cB];         // 8 MB
__device__ __align__(16) float d_nmB[cN * cB];         // 8 MB
__device__ __align__(16) float d_em[cE * cB];          // 16 MB

// ---- grid barrier state ----
__device__ unsigned d_bar_count = 0;
__device__ volatile unsigned d_bar_gen = 0;

// ==================================================================
// PREP kernel: param normalization (log2 domain) + input transpose
// grid partitioned by blockIdx.x: [0,512) norm_input, [512,576) norm_sum,
// 576 norm_root, [577,641) transpose
// ==================================================================
__global__ void __launch_bounds__(256) k_prep(const float* __restrict__ ip,
                                              const float* __restrict__ sp,
                                              const float* __restrict__ rp,
                                              const int*   __restrict__ inputs) {
    int b = blockIdx.x;
    if (b < 512) {
        // --- input params: one warp per (v,k) row of C=256 ---
        int w    = b * 8 + (threadIdx.x >> 5);
        int lane = threadIdx.x & 31;
        const float* row = ip + w * cC;
        float v[8];
        float m = -1e30f;
#pragma unroll
        for (int i = 0; i < 8; i++) {
            v[i] = __log2f(row[lane + i * 32] + EPSF);
            m    = fmaxf(m, v[i]);
        }
#pragma unroll
        for (int o = 16; o; o >>= 1) m = fmaxf(m, __shfl_xor_sync(0xffffffffu, m, o));
        float s = 0.f;
#pragma unroll
        for (int i = 0; i < 8; i++) s += exp2f(v[i] - m);
#pragma unroll
        for (int o = 16; o; o >>= 1) s += __shfl_xor_sync(0xffffffffu, s, o);
        float lse = m + __log2f(s);
#pragma unroll
        for (int i = 0; i < 8; i++) d_lwin[w * cC + lane + i * 32] = v[i] - lse;
    } else if (b < 576) {
        // --- sum params: one thread per (l,n) row of F=16 ---
        int r = (b - 512) * 256 + threadIdx.x;  // 0..16383
        const float4* s4 = reinterpret_cast<const float4*>(sp) + r * 4;
        float v[16];
#pragma unroll
        for (int i = 0; i < 4; i++) {
            float4 x = s4[i];
            v[i * 4 + 0] = __log2f(x.x + EPSF);
            v[i * 4 + 1] = __log2f(x.y + EPSF);
            v[i * 4 + 2] = __log2f(x.z + EPSF);
            v[i * 4 + 3] = __log2f(x.w + EPSF);
        }
        float m = v[0];
#pragma unroll
        for (int i = 1; i < 16; i++) m = fmaxf(m, v[i]);
        float s = 0.f;
#pragma unroll
        for (int i = 0; i < 16; i++) s += exp2f(v[i] - m);
        float lse = m + __log2f(s);
        float4* dst = reinterpret_cast<float4*>(d_lwsum) + r * 4;
#pragma unroll
        for (int i = 0; i < 4; i++) {
            float4 o;
            o.x = v[i * 4 + 0] - lse; o.y = v[i * 4 + 1] - lse;
            o.z = v[i * 4 + 2] - lse; o.w = v[i * 4 + 3] - lse;
            dst[i] = o;
        }
    } else if (b == 576) {
        // --- root params: one block, LSE over N=4096 ---
        __shared__ float red[256];
        int t = threadIdx.x;
        float v[16];
        float m = -1e30f;
#pragma unroll
        for (int i = 0; i < 16; i++) {
            v[i] = __log2f(rp[t + i * 256] + EPSF);
            m    = fmaxf(m, v[i]);
        }
        red[t] = m;
        __syncthreads();
        for (int o = 128; o; o >>= 1) {
            if (t < o) red[t] = fmaxf(red[t], red[t + o]);
            __syncthreads();
        }
        m = red[0];
        __syncthreads();
        float s = 0.f;
#pragma unroll
        for (int i = 0; i < 16; i++) s += exp2f(v[i] - m);
        red[t] = s;
        __syncthreads();
        for (int o = 128; o; o >>= 1) {
            if (t < o) red[t] += red[t + o];
            __syncthreads();
        }
        float lse = m + __log2f(red[0]);
#pragma unroll
        for (int i = 0; i < 16; i++) d_lr[t + i * 256] = v[i] - lse;
    } else {
        // --- transpose inputs (B,V) -> xT (V,B) ---
        int id = (b - 577) * 256 + threadIdx.x;  // 0..16383
        for (int i = id; i < cV * cB; i += 64 * 256) {
            int bb = i >> 7;       // batch
            int vv = i & 127;      // variable
            d_xT[vv * cB + bb] = inputs[i];
        }
    }
}

// ==================================================================
// grid barrier (all GRID blocks resident). __threadfence() both makes
// writes visible (pre) and flushes L1D (post, via CCTL.IVALL).
// ==================================================================
__device__ __forceinline__ void grid_barrier() {
    __syncthreads();
    if (threadIdx.x == 0) {
        __threadfence();
        unsigned gen = d_bar_gen;
        unsigned t   = atomicAdd(&d_bar_count, 1u);
        if (t == GRID - 1) {
            d_bar_count = 0;
            __threadfence();
            d_bar_gen = gen + 1;
        } else {
            while (d_bar_gen == gen) { __nanosleep(64); }
        }
        __threadfence();
    }
    __syncthreads();
}

__device__ __forceinline__ float4 add_s(float4 a, float w) {
    float4 o; o.x = a.x + w; o.y = a.y + w; o.z = a.z + w; o.w = a.w + w; return o;
}

// ==================================================================
// PERSISTENT kernel: gather -> 4x (product, sum) -> root LSE
// ==================================================================
__global__ void __launch_bounds__(NT) k_persist(const int* __restrict__ inputs_unused,
                                                const int* __restrict__ pc,
                                                const int* __restrict__ sci,
                                                float* __restrict__ out) {
    __shared__ float4 s_buf[2048];            // 32 KB, dual-purpose
    float* s_lw = reinterpret_cast<float*>(s_buf);
    const int tid = threadIdx.x;

    // ---------- phase 0: input gather -> d_nmA ----------
    for (int v = blockIdx.x; v < cV; v += GRID) {
        const float4* src = reinterpret_cast<const float4*>(d_lwin + v * cK * cC);
#pragma unroll
        for (int i = 0; i < (cK * cC / 4) / NT; i++) s_buf[tid + i * NT] = src[tid + i * NT];
        __syncthreads();
        int x = d_xT[v * cB + tid];
#pragma unroll
        for (int k = 0; k < cK; k++)
            d_nmA[(v * cK + k) * cB + tid] = s_lw[k * cC + x];
        __syncthreads();
    }
    grid_barrier();

    // ---------- 4 layers ----------
    float* nm_src = d_nmA;
    float* nm_dst = d_nmB;
    for (int l = 0; l < cL; l++) {
        // product layer: em[e][:] = nm[c0][:] + nm[c1][:]
        const int* pcl = pc + l * cE * 2;
        {
            const int sub = tid >> 7;            // 0..3 row within block-iter
            const int g   = tid & 127;           // float4 group
            for (int it = blockIdx.x; it < cE / 4; it += GRID) {
                int e  = it * 4 + sub;
                int c0 = __ldg(pcl + e * 2);
                int c1 = __ldg(pcl + e * 2 + 1);
                float4 a = __ldcg(reinterpret_cast<const float4*>(nm_src + c0 * cB) + g);
                float4 b = __ldcg(reinterpret_cast<const float4*>(nm_src + c1 * cB) + g);
                float4 o;
                o.x = a.x + b.x; o.y = a.y + b.y; o.z = a.z + b.z; o.w = a.w + b.w;
                reinterpret_cast<float4*>(d_em)[e * cB4 + g] = o;
            }
        }
        grid_barrier();

        // sum layer: nm_dst[n][:] = LSE2_f( em[sci[n,f]][:] + lwsum[n,f] )
        const int*   scil = sci + l * cN * cF;
        const float* wl   = d_lwsum + l * cN * cF;
        {
            const int sub = tid >> 7;
            const int g   = tid & 127;
            for (int it = blockIdx.x; it < cN / 4; it += GRID) {
                int n = it * 4 + sub;
                float4 val[cF];
#pragma unroll
                for (int f = 0; f < cF; f++) {
                    int   e = __ldg(scil + n * cF + f);
                    float w = __ldg(wl   + n * cF + f);
                    float4 x = __ldcg(reinterpret_cast<const float4*>(d_em) + e * cB4 + g);
                    val[f] = add_s(x, w);
                }
                float4 m = val[0];
#pragma unroll
                for (int f = 1; f < cF; f++) {
                    m.x = fmaxf(m.x, val[f].x); m.y = fmaxf(m.y, val[f].y);
                    m.z = fmaxf(m.z, val[f].z); m.w = fmaxf(m.w, val[f].w);
                }
                float4 s = make_float4(0.f, 0.f, 0.f, 0.f);
#pragma unroll
                for (int f = 0; f < cF; f++) {
                    s.x += exp2f(val[f].x - m.x); s.y += exp2f(val[f].y - m.y);
                    s.z += exp2f(val[f].z - m.z); s.w += exp2f(val[f].w - m.w);
                }
                float4 o;
                o.x = m.x + __log2f(s.x); o.y = m.y + __log2f(s.y);
                o.z = m.z + __log2f(s.z); o.w = m.w + __log2f(s.w);
                reinterpret_cast<float4*>(nm_dst)[n * cB4 + g] = o;
            }
        }
        grid_barrier();

        float* t = nm_src; nm_src = nm_dst; nm_dst = t;
    }

    // ---------- root: out[b] = ln2 * LSE2_n( nm[n][b] + lr[n] ) ----------
    if (blockIdx.x < cB4) {
        const int g = blockIdx.x;
        float4 m = make_float4(-1e30f, -1e30f, -1e30f, -1e30f);
        for (int n = tid; n < cN; n += NT) {
            float  lr = __ldg(d_lr + n);
            float4 v  = __ldcg(reinterpret_cast<const float4*>(nm_src) + n * cB4 + g);
            m.x = fmaxf(m.x, v.x + lr); m.y = fmaxf(m.y, v.y + lr);
            m.z = fmaxf(m.z, v.z + lr); m.w = fmaxf(m.w, v.w + lr);
        }
        s_buf[tid] = m;
        __syncthreads();
        for (int o = NT / 2; o; o >>= 1) {
            if (tid < o) {
                float4 a = s_buf[tid], b = s_buf[tid + o];
                a.x = fmaxf(a.x, b.x); a.y = fmaxf(a.y, b.y);
                a.z = fmaxf(a.z, b.z); a.w = fmaxf(a.w, b.w);
                s_buf[tid] = a;
            }
            __syncthreads();
        }
        m = s_buf[0];
        __syncthreads();
        float4 s = make_float4(0.f, 0.f, 0.f, 0.f);
        for (int n = tid; n < cN; n += NT) {
            float  lr = __ldg(d_lr + n);
            float4 v  = __ldcg(reinterpret_cast<const float4*>(nm_src) + n * cB4 + g);
            s.x += exp2f(v.x + lr - m.x); s.y += exp2f(v.y + lr - m.y);
            s.z += exp2f(v.z + lr - m.z); s.w += exp2f(v.w + lr - m.w);
        }
        s_buf[tid] = s;
        __syncthreads();
        for (int o = NT / 2; o; o >>= 1) {
            if (tid < o) {
                float4 a = s_buf[tid], b = s_buf[tid + o];
                a.x += b.x; a.y += b.y; a.z += b.z; a.w += b.w;
                s_buf[tid] = a;
            }
            __syncthreads();
        }
        if (tid == 0) {
            float4 r = s_buf[0];
            out[g * 4 + 0] = (m.x + __log2f(r.x)) * LN2F;
            out[g * 4 + 1] = (m.y + __log2f(r.y)) * LN2F;
            out[g * 4 + 2] = (m.z + __log2f(r.z)) * LN2F;
            out[g * 4 + 3] = (m.w + __log2f(r.w)) * LN2F;
        }
    }
}

// ==================================================================
extern "C" void kernel_launch(void* const* d_in, const int* in_sizes, int n_in,
                              void* d_out, int out_size) {
    const int*   inputs = (const int*)d_in[0];    // (B, V)
    const int*   pc     = (const int*)d_in[1];    // (L, E, 2)
    const int*   sci    = (const int*)d_in[2];    // (L, N, F)
    const float* ip     = (const float*)d_in[3];  // (V, K, C)
    const float* sp     = (const float*)d_in[4];  // (L, N, F)
    const float* rp     = (const float*)d_in[5];  // (N,)
    float* out = (float*)d_out;                   // (B,)

    k_prep<<<641, 256>>>(ip, sp, rp, inputs);
    k_persist<<<GRID, NT>>>(inputs, pc, sci, out);
}

// round 3
// speedup vs baseline: 1.0546x; 1.0546x over previous
#include <cuda_runtime.h>

#define EPSF 1e-6f

constexpr int cV = 128, cK = 32, cC = 256;
constexpr int cL = 4, cN = 4096, cF = 16;
constexpr int cE = 8192, cB = 512;
constexpr int cB2 = cB / 2;          // 256 float2 groups per row
constexpr int cB4 = cB / 4;          // 128 float4 groups per row
constexpr int NT   = 256;
constexpr int BPSM = 4;              // blocks per SM (guaranteed via launch_bounds)
constexpr int GRID = 148 * BPSM;     // 592 persistent blocks
constexpr float LN2F = 0.69314718055994530942f;

// ---- scratch (static __device__ per allocation rules) ----
__device__ __align__(16) float d_lwin[cV * cK * cC];   // 4 MB  (log2 domain)
__device__ __align__(16) float d_lwsum[cL * cN * cF];  // 1 MB  (log2 domain)
__device__ __align__(16) float d_lr[cN];               // 16 KB (log2 domain)
__device__ __align__(16) int   d_xT[cV * cB];          // 256 KB transposed inputs
__device__ __align__(16) float d_nmA[cN * cB];         // 8 MB
__device__ __align__(16) float d_nmB[cN * cB];         // 8 MB
__device__ __align__(16) float d_em[cE * cB];          // 16 MB

// ---- grid barrier state ----
__device__ unsigned d_bar_count = 0;
__device__ volatile unsigned d_bar_gen = 0;

// ---- single-instruction MUFU ops independent of compile flags ----
__device__ __forceinline__ float ex2(float x) {
    float y; asm("ex2.approx.ftz.f32 %0, %1;" : "=f"(y) : "f"(x)); return y;
}
__device__ __forceinline__ float lg2(float x) {
    float y; asm("lg2.approx.ftz.f32 %0, %1;" : "=f"(y) : "f"(x)); return y;
}

// ==================================================================
// PREP kernel: param normalization (log2 domain) + input transpose
// ==================================================================
__global__ void __launch_bounds__(256) k_prep(const float* __restrict__ ip,
                                              const float* __restrict__ sp,
                                              const float* __restrict__ rp,
                                              const int*   __restrict__ inputs) {
    int b = blockIdx.x;
    if (b < 512) {
        // --- input params: one warp per (v,k) row of C=256 ---
        int w    = b * 8 + (threadIdx.x >> 5);
        int lane = threadIdx.x & 31;
        const float* row = ip + w * cC;
        float v[8];
        float m = -1e30f;
#pragma unroll
        for (int i = 0; i < 8; i++) {
            v[i] = lg2(row[lane + i * 32] + EPSF);
            m    = fmaxf(m, v[i]);
        }
#pragma unroll
        for (int o = 16; o; o >>= 1) m = fmaxf(m, __shfl_xor_sync(0xffffffffu, m, o));
        float s = 0.f;
#pragma unroll
        for (int i = 0; i < 8; i++) s += ex2(v[i] - m);
#pragma unroll
        for (int o = 16; o; o >>= 1) s += __shfl_xor_sync(0xffffffffu, s, o);
        float lse = m + lg2(s);
#pragma unroll
        for (int i = 0; i < 8; i++) d_lwin[w * cC + lane + i * 32] = v[i] - lse;
    } else if (b < 576) {
        // --- sum params: one thread per (l,n) row of F=16 ---
        int r = (b - 512) * 256 + threadIdx.x;
        const float4* s4 = reinterpret_cast<const float4*>(sp) + r * 4;
        float v[16];
#pragma unroll
        for (int i = 0; i < 4; i++) {
            float4 x = s4[i];
            v[i * 4 + 0] = lg2(x.x + EPSF);
            v[i * 4 + 1] = lg2(x.y + EPSF);
            v[i * 4 + 2] = lg2(x.z + EPSF);
            v[i * 4 + 3] = lg2(x.w + EPSF);
        }
        float m = v[0];
#pragma unroll
        for (int i = 1; i < 16; i++) m = fmaxf(m, v[i]);
        float s = 0.f;
#pragma unroll
        for (int i = 0; i < 16; i++) s += ex2(v[i] - m);
        float lse = m + lg2(s);
        float4* dst = reinterpret_cast<float4*>(d_lwsum) + r * 4;
#pragma unroll
        for (int i = 0; i < 4; i++) {
            float4 o;
            o.x = v[i * 4 + 0] - lse; o.y = v[i * 4 + 1] - lse;
            o.z = v[i * 4 + 2] - lse; o.w = v[i * 4 + 3] - lse;
            dst[i] = o;
        }
    } else if (b == 576) {
        // --- root params: one block, LSE over N=4096 ---
        __shared__ float red[256];
        int t = threadIdx.x;
        float v[16];
        float m = -1e30f;
#pragma unroll
        for (int i = 0; i < 16; i++) {
            v[i] = lg2(rp[t + i * 256] + EPSF);
            m    = fmaxf(m, v[i]);
        }
        red[t] = m;
        __syncthreads();
        for (int o = 128; o; o >>= 1) {
            if (t < o) red[t] = fmaxf(red[t], red[t + o]);
            __syncthreads();
        }
        m = red[0];
        __syncthreads();
        float s = 0.f;
#pragma unroll
        for (int i = 0; i < 16; i++) s += ex2(v[i] - m);
        red[t] = s;
        __syncthreads();
        for (int o = 128; o; o >>= 1) {
            if (t < o) red[t] += red[t + o];
            __syncthreads();
        }
        float lse = m + lg2(red[0]);
#pragma unroll
        for (int i = 0; i < 16; i++) d_lr[t + i * 256] = v[i] - lse;
    } else {
        // --- transpose inputs (B,V) -> xT (V,B) ---
        int id = (b - 577) * 256 + threadIdx.x;
        for (int i = id; i < cV * cB; i += 64 * 256) {
            int bb = i >> 7;
            int vv = i & 127;
            d_xT[vv * cB + bb] = inputs[i];
        }
    }
}

// ==================================================================
// grid barrier (all GRID blocks resident). __threadfence() makes writes
// visible (pre) and flushes L1D (post, via CCTL.IVALL), so plain
// L1-cached loads after the barrier are coherent.
// ==================================================================
__device__ __forceinline__ void grid_barrier() {
    __syncthreads();
    if (threadIdx.x == 0) {
        __threadfence();
        unsigned gen = d_bar_gen;
        unsigned t   = atomicAdd(&d_bar_count, 1u);
        if (t == GRID - 1) {
            d_bar_count = 0;
            __threadfence();
            d_bar_gen = gen + 1;
        } else {
            while (d_bar_gen == gen) { __nanosleep(64); }
        }
        __threadfence();
    }
    __syncthreads();
}

// ==================================================================
// PERSISTENT kernel: gather -> 4x (product, sum) -> root LSE
// 256 thr/block, 4 blocks/SM forced -> 32 warps/SM
// ==================================================================
__global__ void __launch_bounds__(NT, BPSM) k_persist(const int* __restrict__ pc,
                                                      const int* __restrict__ sci,
                                                      float* __restrict__ out) {
    __shared__ int    s_e[cF];
    __shared__ float  s_w[cF];
    __shared__ float2 s_red[NT];
    const int t = threadIdx.x;

    // ---------- phase 0: input gather -> d_nmA ----------
    // nm[(v*K+k)*B + b] = lwin[v*K+k, xT[v*B+b]]
    {
        const int stride = GRID * NT;
        for (int i = blockIdx.x * NT + t; i < cN * cB; i += stride) {
            int b  = i & (cB - 1);
            int vk = i >> 9;
            int v  = vk >> 5;
            int x  = d_xT[v * cB + b];
            d_nmA[i] = d_lwin[vk * cC + x];
        }
    }
    grid_barrier();

    // ---------- 4 layers ----------
    float* nm_src = d_nmA;
    float* nm_dst = d_nmB;
    for (int l = 0; l < cL; l++) {
        // product layer: em[e][:] = nm[c0][:] + nm[c1][:]  (float4, 2 rows/iter)
        const int* pcl = pc + l * cE * 2;
        {
            const int sub = t >> 7;          // 0..1
            const int g   = t & 127;         // float4 group
            for (int it = blockIdx.x; it < cE / 2; it += GRID) {
                int e  = it * 2 + sub;
                int c0 = __ldg(pcl + e * 2);
                int c1 = __ldg(pcl + e * 2 + 1);
                float4 a = reinterpret_cast<const float4*>(nm_src + c0 * cB)[g];
                float4 b = reinterpret_cast<const float4*>(nm_src + c1 * cB)[g];
                float4 o;
                o.x = a.x + b.x; o.y = a.y + b.y; o.z = a.z + b.z; o.w = a.w + b.w;
                reinterpret_cast<float4*>(d_em)[e * cB4 + g] = o;
            }
        }
        grid_barrier();

        // sum layer: nm_dst[n][:] = LSE2_f( em[sci[n,f]][:] + lwsum[n,f] )
        // one n per block-iter; indices/weights in SMEM; float2 per thread
        const int*   scil = sci + l * cN * cF;
        const float* wl   = d_lwsum + l * cN * cF;
        {
            const float2* emp = reinterpret_cast<const float2*>(d_em);
            for (int n = blockIdx.x; n < cN; n += GRID) {
                if (t < cF) {
                    s_e[t] = scil[n * cF + t] * cB2;   // pre-scaled row offset
                    s_w[t] = wl[n * cF + t];
                }
                __syncthreads();
                float2 val[cF];
#pragma unroll
                for (int f = 0; f < cF; f++) {
                    float2 x = emp[s_e[f] + t];
                    float  w = s_w[f];
                    val[f].x = x.x + w; val[f].y = x.y + w;
                }
                float2 m = val[0];
#pragma unroll
                for (int f = 1; f < cF; f++) {
                    m.x = fmaxf(m.x, val[f].x);
                    m.y = fmaxf(m.y, val[f].y);
                }
                float2 s = make_float2(0.f, 0.f);
#pragma unroll
                for (int f = 0; f < cF; f++) {
                    s.x += ex2(val[f].x - m.x);
                    s.y += ex2(val[f].y - m.y);
                }
                float2 o;
                o.x = m.x + lg2(s.x);
                o.y = m.y + lg2(s.y);
                reinterpret_cast<float2*>(nm_dst)[n * cB2 + t] = o;
                __syncthreads();
            }
        }
        grid_barrier();

        float* tmp = nm_src; nm_src = nm_dst; nm_dst = tmp;
    }

    // ---------- root: out[b] = ln2 * LSE2_n( nm[n][b] + lr[n] ) ----------
    if (blockIdx.x < cB2) {
        const int g = blockIdx.x;             // float2 batch group
        const float2* nmp = reinterpret_cast<const float2*>(nm_src);
        float2 v[16];
        float2 m = make_float2(-1e30f, -1e30f);
#pragma unroll
        for (int k = 0; k < 16; k++) {
            int   n  = t + k * NT;
            float lr = __ldg(d_lr + n);
            float2 x = nmp[n * cB2 + g];
            v[k].x = x.x + lr; v[k].y = x.y + lr;
            m.x = fmaxf(m.x, v[k].x); m.y = fmaxf(m.y, v[k].y);
        }
        s_red[t] = m;
        __syncthreads();
        for (int o = NT / 2; o; o >>= 1) {
            if (t < o) {
                float2 a = s_red[t], b2 = s_red[t + o];
                a.x = fmaxf(a.x, b2.x); a.y = fmaxf(a.y, b2.y);
                s_red[t] = a;
            }
            __syncthreads();
        }
        m = s_red[0];
        __syncthreads();
        float2 s = make_float2(0.f, 0.f);
#pragma unroll
        for (int k = 0; k < 16; k++) {
            s.x += ex2(v[k].x - m.x);
            s.y += ex2(v[k].y - m.y);
        }
        s_red[t] = s;
        __syncthreads();
        for (int o = NT / 2; o; o >>= 1) {
            if (t < o) {
                float2 a = s_red[t], b2 = s_red[t + o];
                a.x += b2.x; a.y += b2.y;
                s_red[t] = a;
            }
            __syncthreads();
        }
        if (t == 0) {
            float2 r = s_red[0];
            out[g * 2 + 0] = (m.x + lg2(r.x)) * LN2F;
            out[g * 2 + 1] = (m.y + lg2(r.y)) * LN2F;
        }
    }
}

// ==================================================================
extern "C" void kernel_launch(void* const* d_in, const int* in_sizes, int n_in,
                              void* d_out, int out_size) {
    const int*   inputs = (const int*)d_in[0];    // (B, V)
    const int*   pc     = (const int*)d_in[1];    // (L, E, 2)
    const int*   sci    = (const int*)d_in[2];    // (L, N, F)
    const float* ip     = (const float*)d_in[3];  // (V, K, C)
    const float* sp     = (const float*)d_in[4];  // (L, N, F)
    const float* rp     = (const float*)d_in[5];  // (N,)
    float* out = (float*)d_out;                   // (B,)

    k_prep<<<641, 256>>>(ip, sp, rp, inputs);
    k_persist<<<GRID, NT>>>(pc, sci, out);
}